// round 8
// baseline (speedup 1.0000x reference)
#include <cuda_runtime.h>
#include <math.h>

typedef unsigned long long u64;

#define BATCH  512
#define TLEN   1024
#define HID    64
#define M_TOTAL (BATCH*TLEN)
#define CHUNKS 8
#define CT     (TLEN/CHUNKS)          // 128 steps per chunk

// Block geometry: scan2 = 2 rows/block -> 256 blocks per (l,c) group;
// gemm4 = 4 row-chunks/block -> 128 blocks per (l,c) group; FC ditto.
#define NG4    128                    // gemm4 groups per (l,c)
#define NS2    256                    // scan2 groups per (l,c)
// total blocks: 32 (l,c) pairs * (128 + 256) + 8 chunks * 128 FC = 13312
#define BLOCKS_TOTAL (32*(NG4+NS2) + CHUNKS*NG4)

// Per-layer scratch.
__device__ __align__(16) float g_pre [4][M_TOTAL*HID];
__device__ __align__(16) float g_hout[4][M_TOTAL*HID];
__device__ __align__(16) float g_hst [4][BATCH*HID];    // h carry between chunks

// Dependency flags (per row-group).
__device__ int gflag4[4][CHUNKS][NG4];   // pre(l,c, 4-row group) ready
__device__ int sflag2[4][CHUNKS][NS2];   // h  (l,c, 2-row group) ready

__device__ __forceinline__ int ld_acq(const int* p) {
    int v;
    asm volatile("ld.acquire.gpu.global.b32 %0, [%1];" : "=r"(v) : "l"(p) : "memory");
    return v;
}
__device__ __forceinline__ void st_rel(int* p, int v) {
    asm volatile("st.release.gpu.global.b32 [%0], %1;" :: "l"(p), "r"(v) : "memory");
}

__device__ __forceinline__ u64 pk2(float x, float y) {
    u64 r; asm("mov.b64 %0,{%1,%2};" : "=l"(r) : "f"(x), "f"(y)); return r;
}
__device__ __forceinline__ void upk2(u64 v, float &x, float &y) {
    asm("mov.b64 {%0,%1},%2;" : "=f"(x), "=f"(y) : "l"(v));
}
#define FMA2(d,a,b,c) asm("fma.rn.f32x2 %0,%1,%2,%3;" : "=l"(d) : "l"(a), "l"(b), "l"(c))
#define ADD2(d,a,b)   asm("add.rn.f32x2 %0,%1,%2;"    : "=l"(d) : "l"(a), "l"(b))

__device__ __forceinline__ float tanh_fast(float x) {
    float xc = fminf(fmaxf(x, -15.0f), 15.0f);
    float e;
    asm("ex2.approx.f32 %0, %1;" : "=f"(e) : "f"(xc * 2.885390081777927f));
    float r;
    asm("rcp.approx.f32 %0, %1;" : "=f"(r) : "f"(e + 1.0f));
    return (e - 1.0f) * r;
}

// ============================================================================
// GEMM tile body (proven): 128 threads, 128 rows x 64 cols, 8x8 per thread.
// Safe to call repeatedly (leading __syncthreads guards smem reuse).
// ============================================================================
__device__ __forceinline__ void gemm_body(
    const float* __restrict__ X, const float* __restrict__ W,
    const float* __restrict__ b1, const float* __restrict__ b2,
    float* __restrict__ Out, int K, long m0)
{
    __shared__ __align__(16) u64 Xd[128*32];
    __shared__ __align__(16) u64 Wp[32*32];

    const int tid = threadIdx.x;
    const int nt  = tid & 7;
    const int mt  = tid >> 3;
    const int np0 = nt * 4;
    const int mr  = mt * 8;
    const int xsw = (mt & 3) << 2;

    u64 acc[8][4];
    {
        u64 bias[4];
        #pragma unroll
        for (int p = 0; p < 4; p++) {
            int n = (np0 + p) * 2;
            float v0 = b1[n], v1 = b1[n+1];
            if (b2) { v0 += b2[n]; v1 += b2[n+1]; }
            bias[p] = pk2(v0, v1);
        }
        #pragma unroll
        for (int i = 0; i < 8; i++)
            #pragma unroll
            for (int p = 0; p < 4; p++) acc[i][p] = bias[p];
    }

    #pragma unroll
    for (int kh = 0; kh < 2; kh++) {
        const int kbase = kh * 32;
        __syncthreads();

        #pragma unroll 8
        for (int i = 0; i < 32; i++) {
            int idx = i * 128 + tid;
            int m  = idx >> 5;
            int kk = idx & 31;
            int k  = kbase + kk;
            float v = (k < K) ? X[(m0 + m) * (long)K + k] : 0.f;
            Xd[m * 32 + (kk ^ (((m >> 3) & 3) << 2))] = pk2(v, v);
        }
        #pragma unroll
        for (int i = 0; i < 8; i++) {
            int idx = i * 128 + tid;
            int np = idx >> 5;
            int kk = idx & 31;
            int k  = kbase + kk;
            float w0 = 0.f, w1 = 0.f;
            if (k < K) {
                w0 = W[(2*np)   * (long)K + k];
                w1 = W[(2*np+1) * (long)K + k];
            }
            Wp[kk * 32 + (np ^ ((kk & 7) << 2))] = pk2(w0, w1);
        }
        __syncthreads();

        #pragma unroll 8
        for (int kk = 0; kk < 32; kk++) {
            int wbase = kk * 32 + (np0 ^ ((kk & 7) << 2));
            ulonglong2 wA = *reinterpret_cast<const ulonglong2*>(&Wp[wbase]);
            ulonglong2 wB = *reinterpret_cast<const ulonglong2*>(&Wp[wbase + 2]);
            const u64* xcol = &Xd[mr * 32 + (kk ^ xsw)];
            #pragma unroll
            for (int i = 0; i < 8; i++) {
                u64 xv = xcol[i * 32];
                FMA2(acc[i][0], xv, wA.x, acc[i][0]);
                FMA2(acc[i][1], xv, wA.y, acc[i][1]);
                FMA2(acc[i][2], xv, wB.x, acc[i][2]);
                FMA2(acc[i][3], xv, wB.y, acc[i][3]);
            }
        }
    }

    const int n0 = np0 * 2;
    #pragma unroll
    for (int i = 0; i < 8; i++) {
        float* dst = &Out[(m0 + mr + i) * 64 + n0];
        ulonglong2 v0, v1;
        v0.x = acc[i][0]; v0.y = acc[i][1];
        v1.x = acc[i][2]; v1.y = acc[i][3];
        *reinterpret_cast<ulonglong2*>(dst)     = v0;
        *reinterpret_cast<ulonglong2*>(dst + 4) = v1;
    }
}

__global__ void zero_flags()
{
    int idx = blockIdx.x * blockDim.x + threadIdx.x;
    const int NG = 4 * CHUNKS * NG4;
    const int NS = 4 * CHUNKS * NS2;
    if (idx < NG) (&gflag4[0][0][0])[idx] = 0;
    if (idx < NS) (&sflag2[0][0][0])[idx] = 0;
}

// ============================================================================
// Megakernel, DIAGONAL-major bid order. diag d = c + l (FC at d = c + 4).
// Within diag d: for l = lmin..lmax: [gemm4_l (128), scan2_l (256)]; then FC (128).
// All deps land at strictly earlier bids -> deadlock-free under in-order CTA
// scheduling; window now spans layer boundaries -> cross-chunk pipelining.
// ============================================================================
__global__ void __launch_bounds__(128, 4) mega(
    const float* __restrict__ x,
    const float* __restrict__ Wih0, const float* __restrict__ Whh0,
    const float* __restrict__ bih0, const float* __restrict__ bhh0,
    const float* __restrict__ Wih,  const float* __restrict__ Whh,
    const float* __restrict__ bih,  const float* __restrict__ bhh,
    const float* __restrict__ Wfc,  const float* __restrict__ bfc,
    float* __restrict__ out)
{
    const int tid = threadIdx.x;

    // ---- decode bid -> (kind, l, c, grp) via diagonal walk
    int rem = blockIdx.x;
    int kind = -1, l = 0, c = 0, grp = 0;
    #pragma unroll 1
    for (int d = 0; d < 12 && kind < 0; d++) {
        int lmin = (d > 7) ? d - 7 : 0;
        int lmax = (d < 3) ? d : 3;
        #pragma unroll 1
        for (int ll = lmin; ll <= lmax && kind < 0; ll++) {
            if (rem < NG4) { kind = 0; l = ll; c = d - ll; grp = rem; break; }
            rem -= NG4;
            if (rem < NS2) { kind = 1; l = ll; c = d - ll; grp = rem; break; }
            rem -= NS2;
        }
        if (kind < 0 && d >= 4) {
            if (rem < NG4) { kind = 2; c = d - 4; grp = rem; }
            else rem -= NG4;
        }
    }

    const int t0 = c * CT;

    if (kind == 0 || kind == 2) {
        // ================= GEMM4 / FC: 4 consecutive row-chunks =================
        const int ldep = (kind == 2) ? 3 : l - 1;   // dep layer (scan output)
        if (tid == 0 && (kind == 2 || l > 0)) {
            while (ld_acq(&sflag2[ldep][c][2*grp    ]) == 0) __nanosleep(128);
            while (ld_acq(&sflag2[ldep][c][2*grp + 1]) == 0) __nanosleep(128);
            __threadfence();
        }
        __syncthreads();

        const float* X; const float* W; const float* b1; const float* b2;
        float* Out; int K;
        if (kind == 2) {
            X = &g_hout[3][0]; W = Wfc; b1 = bfc; b2 = nullptr; Out = out; K = 64;
        } else if (l == 0) {
            X = x; W = Wih0; b1 = bih0; b2 = bhh0; Out = &g_pre[0][0]; K = 52;
        } else {
            X = &g_hout[l-1][0]; W = Wih + (l-1)*4096;
            b1 = bih + (l-1)*64;  b2 = bhh + (l-1)*64;
            Out = &g_pre[l][0]; K = 64;
        }

        #pragma unroll 1
        for (int rr = 0; rr < 4; rr++) {
            long m0 = (long)(4*grp + rr) * TLEN + t0;
            gemm_body(X, W, b1, b2, Out, K, m0);
        }

        if (kind == 0) {
            __threadfence();
            __syncthreads();
            if (tid == 0) st_rel(&gflag4[l][c][grp], 1);
        }
        return;
    }

    // ================= SCAN2: 2 rows (r = tid>>6), R5 p4 body =================
    const float* Whh_l = (l == 0) ? Whh0 : Whh + (l-1)*4096;
    float* pre  = &g_pre [l][0];
    float* hout = &g_hout[l][0];
    float* hst  = &g_hst [l][0];

    __shared__ __align__(16) float  hbuf[2][2][64];   // [phase][row][col]
    __shared__ __align__(16) float4 psum[2][2][16];   // [row][warp-half][jg]

    const int r    = tid >> 6;       // row within block
    const int lt   = tid & 63;
    const int W32  = lt >> 5;
    const int lane = tid & 31;
    const int s2   = lane >> 4;
    const int jg   = lane & 15;
    const int K0   = W32 * 32 + s2 * 16;
    const long b   = 2L*grp + r;

    if (tid == 0) {
        while (ld_acq(&gflag4[l][c][grp >> 1]) == 0) __nanosleep(128);
    }
    if (tid == 1 && c > 0) {
        while (ld_acq(&sflag2[l][c-1][grp]) == 0) __nanosleep(128);
    }
    if (tid < 2) __threadfence();
    __syncthreads();

    float h0v = (c == 0) ? 0.f : __ldcg(&hst[b*64 + lt]);
    hbuf[0][r][lt] = h0v;
    hbuf[1][r][lt] = h0v;

    u64 w2[4][8];
    #pragma unroll
    for (int o = 0; o < 4; o++) {
        const float4* wr = reinterpret_cast<const float4*>(Whh_l + (4*jg + o)*64 + K0);
        #pragma unroll
        for (int q = 0; q < 4; q++) {
            float4 w = __ldg(&wr[q]);
            w2[o][2*q]   = pk2(w.x, w.y);
            w2[o][2*q+1] = pk2(w.z, w.w);
        }
    }

    const float* prow = pre  + (b * TLEN + t0) * 64 + lt;
    float*       orow = hout + (b * TLEN + t0) * 64 + lt;

    float pb[8];
    #pragma unroll
    for (int q = 0; q < 8; q++) pb[q] = __ldg(&prow[q * 64]);
    __syncthreads();

    #pragma unroll 8
    for (int t = 0; t < CT; t++) {
        float cur = pb[t & 7];
        if (t + 8 < CT) pb[t & 7] = __ldg(&prow[(long)(t + 8) * 64]);

        const ulonglong2* H2 = reinterpret_cast<const ulonglong2*>(&hbuf[t & 1][r][K0]);
        ulonglong2 hA = H2[0];
        ulonglong2 hB = H2[1];
        ulonglong2 hC = H2[2];
        ulonglong2 hD = H2[3];

        float P[4];
        #pragma unroll
        for (int o = 0; o < 4; o++) {
            u64 a0 = 0ull, a1 = 0ull;
            FMA2(a0, hA.x, w2[o][0], a0);
            FMA2(a1, hA.y, w2[o][1], a1);
            FMA2(a0, hB.x, w2[o][2], a0);
            FMA2(a1, hB.y, w2[o][3], a1);
            FMA2(a0, hC.x, w2[o][4], a0);
            FMA2(a1, hC.y, w2[o][5], a1);
            FMA2(a0, hD.x, w2[o][6], a0);
            FMA2(a1, hD.y, w2[o][7], a1);
            ADD2(a0, a0, a1);
            float lo, hi; upk2(a0, lo, hi);
            P[o] = lo + hi;
        }
        #pragma unroll
        for (int o = 0; o < 4; o++)
            P[o] += __shfl_xor_sync(0xffffffffu, P[o], 16);

        if (s2 == 0)
            psum[r][W32][jg] = make_float4(P[0], P[1], P[2], P[3]);
        __syncthreads();

        float part = reinterpret_cast<const float*>(&psum[r][0][0])[lt]
                   + reinterpret_cast<const float*>(&psum[r][1][0])[lt];
        float h = tanh_fast(cur + part);

        orow[(long)t * 64] = h;
        hbuf[(t & 1) ^ 1][r][lt] = h;
        __syncthreads();
    }

    hst[b*64 + lt] = hbuf[0][r][lt];   // CT even -> final h in phase 0

    __threadfence();
    __syncthreads();
    if (tid == 0) st_rel(&sflag2[l][c][grp], 1);
}

extern "C" void kernel_launch(void* const* d_in, const int* in_sizes, int n_in,
                              void* d_out, int out_size)
{
    const float* x    = (const float*)d_in[0];
    const float* Wih0 = (const float*)d_in[1];
    const float* Whh0 = (const float*)d_in[2];
    const float* bih0 = (const float*)d_in[3];
    const float* bhh0 = (const float*)d_in[4];
    const float* Wih  = (const float*)d_in[5];
    const float* Whh  = (const float*)d_in[6];
    const float* bih  = (const float*)d_in[7];
    const float* bhh  = (const float*)d_in[8];
    const float* Wfc  = (const float*)d_in[9];
    const float* bfc  = (const float*)d_in[10];
    float* out = (float*)d_out;

    zero_flags<<<(4*CHUNKS*NS2 + 255)/256, 256>>>();
    mega<<<BLOCKS_TOTAL, 128>>>(x, Wih0, Whh0, bih0, bhh0,
                                Wih, Whh, bih, bhh, Wfc, bfc, out);
}

// round 9
// speedup vs baseline: 1.3214x; 1.3214x over previous
#include <cuda_runtime.h>
#include <math.h>

typedef unsigned long long u64;

#define BATCH  512
#define TLEN   1024
#define HID    64
#define M_TOTAL (BATCH*TLEN)
#define CHUNKS 8
#define CT     (TLEN/CHUNKS)          // 128 steps per chunk

// per chunk: gemm groups 512 blocks, scan groups 256 blocks (2 rows/block), fc 512
#define CHUNK_BLOCKS (4*512 + 4*256 + 512)     // 3584
#define BLOCKS_TOTAL (CHUNKS*CHUNK_BLOCKS)     // 28672

// Per-layer scratch.
__device__ __align__(16) float g_pre [4][M_TOTAL*HID];
__device__ __align__(16) float g_hout[4][M_TOTAL*HID];
__device__ __align__(16) float g_hst [4][BATCH*HID];    // h carry between chunks

// Dependency flags: per (layer, chunk, batch-row).
__device__ int gflag[4][CHUNKS][BATCH];
__device__ int sflag[4][CHUNKS][BATCH];

__device__ __forceinline__ int ld_acq(const int* p) {
    int v;
    asm volatile("ld.acquire.gpu.global.b32 %0, [%1];" : "=r"(v) : "l"(p) : "memory");
    return v;
}
__device__ __forceinline__ void st_rel(int* p, int v) {
    asm volatile("st.release.gpu.global.b32 [%0], %1;" :: "l"(p), "r"(v) : "memory");
}
__device__ __forceinline__ void bar_sync(int id) {
    asm volatile("bar.sync %0, 64;" :: "r"(id) : "memory");
}

__device__ __forceinline__ u64 pk2(float x, float y) {
    u64 r; asm("mov.b64 %0,{%1,%2};" : "=l"(r) : "f"(x), "f"(y)); return r;
}
__device__ __forceinline__ void upk2(u64 v, float &x, float &y) {
    asm("mov.b64 {%0,%1},%2;" : "=f"(x), "=f"(y) : "l"(v));
}
#define FMA2(d,a,b,c) asm("fma.rn.f32x2 %0,%1,%2,%3;" : "=l"(d) : "l"(a), "l"(b), "l"(c))
#define ADD2(d,a,b)   asm("add.rn.f32x2 %0,%1,%2;"    : "=l"(d) : "l"(a), "l"(b))

__device__ __forceinline__ float tanh_fast(float x) {
    float xc = fminf(fmaxf(x, -15.0f), 15.0f);
    float e;
    asm("ex2.approx.f32 %0, %1;" : "=f"(e) : "f"(xc * 2.885390081777927f));
    float r;
    asm("rcp.approx.f32 %0, %1;" : "=f"(r) : "f"(e + 1.0f));
    return (e - 1.0f) * r;
}

// ============================================================================
// GEMM tile body (proven): 128 threads, 128 rows x 64 cols, 8x8 per thread.
// ============================================================================
__device__ __forceinline__ void gemm_body(
    const float* __restrict__ X, const float* __restrict__ W,
    const float* __restrict__ b1, const float* __restrict__ b2,
    float* __restrict__ Out, int K, long m0)
{
    __shared__ __align__(16) u64 Xd[128*32];
    __shared__ __align__(16) u64 Wp[32*32];

    const int tid = threadIdx.x;
    const int nt  = tid & 7;
    const int mt  = tid >> 3;
    const int np0 = nt * 4;
    const int mr  = mt * 8;
    const int xsw = (mt & 3) << 2;

    u64 acc[8][4];
    {
        u64 bias[4];
        #pragma unroll
        for (int p = 0; p < 4; p++) {
            int n = (np0 + p) * 2;
            float v0 = b1[n], v1 = b1[n+1];
            if (b2) { v0 += b2[n]; v1 += b2[n+1]; }
            bias[p] = pk2(v0, v1);
        }
        #pragma unroll
        for (int i = 0; i < 8; i++)
            #pragma unroll
            for (int p = 0; p < 4; p++) acc[i][p] = bias[p];
    }

    #pragma unroll
    for (int kh = 0; kh < 2; kh++) {
        const int kbase = kh * 32;
        __syncthreads();

        #pragma unroll 8
        for (int i = 0; i < 32; i++) {
            int idx = i * 128 + tid;
            int m  = idx >> 5;
            int kk = idx & 31;
            int k  = kbase + kk;
            float v = (k < K) ? X[(m0 + m) * (long)K + k] : 0.f;
            Xd[m * 32 + (kk ^ (((m >> 3) & 3) << 2))] = pk2(v, v);
        }
        #pragma unroll
        for (int i = 0; i < 8; i++) {
            int idx = i * 128 + tid;
            int np = idx >> 5;
            int kk = idx & 31;
            int k  = kbase + kk;
            float w0 = 0.f, w1 = 0.f;
            if (k < K) {
                w0 = W[(2*np)   * (long)K + k];
                w1 = W[(2*np+1) * (long)K + k];
            }
            Wp[kk * 32 + (np ^ ((kk & 7) << 2))] = pk2(w0, w1);
        }
        __syncthreads();

        #pragma unroll 8
        for (int kk = 0; kk < 32; kk++) {
            int wbase = kk * 32 + (np0 ^ ((kk & 7) << 2));
            ulonglong2 wA = *reinterpret_cast<const ulonglong2*>(&Wp[wbase]);
            ulonglong2 wB = *reinterpret_cast<const ulonglong2*>(&Wp[wbase + 2]);
            const u64* xcol = &Xd[mr * 32 + (kk ^ xsw)];
            #pragma unroll
            for (int i = 0; i < 8; i++) {
                u64 xv = xcol[i * 32];
                FMA2(acc[i][0], xv, wA.x, acc[i][0]);
                FMA2(acc[i][1], xv, wA.y, acc[i][1]);
                FMA2(acc[i][2], xv, wB.x, acc[i][2]);
                FMA2(acc[i][3], xv, wB.y, acc[i][3]);
            }
        }
    }

    const int n0 = np0 * 2;
    #pragma unroll
    for (int i = 0; i < 8; i++) {
        float* dst = &Out[(m0 + mr + i) * 64 + n0];
        ulonglong2 v0, v1;
        v0.x = acc[i][0]; v0.y = acc[i][1];
        v1.x = acc[i][2]; v1.y = acc[i][3];
        *reinterpret_cast<ulonglong2*>(dst)     = v0;
        *reinterpret_cast<ulonglong2*>(dst + 4) = v1;
    }
}

__global__ void zero_flags()
{
    int idx = blockIdx.x * blockDim.x + threadIdx.x;
    const int N = 4 * CHUNKS * BATCH;
    if (idx < N) { (&gflag[0][0][0])[idx] = 0; (&sflag[0][0][0])[idx] = 0; }
}

// ============================================================================
// Megakernel, CHUNK-major order (R7, proven):
//   per chunk c: g0 gemm0(512) g1 scan0(256) g2 gemm1(512) ... g7 scan3(256) g8 fc(512)
// Scan blocks: 128 thr = 2 DECOUPLED rows; each row syncs via its own named
// barrier (bar.sync 1+r, 64). "s4j1" layout: lane=(ks=lane>>3, og=lane&7),
// 4 outputs x 16k per lane; 2x shfl_xor (8,16) full in-warp k-reduction;
// each lane finalizes output 4og+ks. ONE barrier per step, no psum smem.
// ============================================================================
__global__ void __launch_bounds__(128, 4) mega(
    const float* __restrict__ x,
    const float* __restrict__ Wih0, const float* __restrict__ Whh0,
    const float* __restrict__ bih0, const float* __restrict__ bhh0,
    const float* __restrict__ Wih,  const float* __restrict__ Whh,
    const float* __restrict__ bih,  const float* __restrict__ bhh,
    const float* __restrict__ Wfc,  const float* __restrict__ bfc,
    float* __restrict__ out)
{
    const int tid = threadIdx.x;
    const int c   = blockIdx.x / CHUNK_BLOCKS;
    int rem       = blockIdx.x % CHUNK_BLOCKS;
    const int t0  = c * CT;

    // decode group within chunk: alternating 512 (gemm) / 256 (scan), then 512 fc
    int kind = -1, l = 0, grp = 0;      // kind 0=gemm,1=scan,2=fc
    #pragma unroll
    for (int ll = 0; ll < 4; ll++) {
        if (kind < 0) {
            if (rem < 512) { kind = 0; l = ll; grp = rem; }
            else {
                rem -= 512;
                if (rem < 256) { kind = 1; l = ll; grp = rem; }
                else rem -= 256;
            }
        }
    }
    if (kind < 0) { kind = 2; grp = rem; }

    if (kind == 0 || kind == 2) {
        // ================= GEMM / FC: one 128-row tile (batch row grp) =========
        const int b = grp;
        if (tid == 0) {
            if (kind == 2) { while (ld_acq(&sflag[3][c][b])   == 0) __nanosleep(64); __threadfence(); }
            else if (l > 0){ while (ld_acq(&sflag[l-1][c][b]) == 0) __nanosleep(64); __threadfence(); }
        }
        __syncthreads();

        const float* X; const float* W; const float* b1; const float* b2;
        float* Out; int K;
        if (kind == 2) {
            X = &g_hout[3][0]; W = Wfc; b1 = bfc; b2 = nullptr; Out = out; K = 64;
        } else if (l == 0) {
            X = x; W = Wih0; b1 = bih0; b2 = bhh0; Out = &g_pre[0][0]; K = 52;
        } else {
            X = &g_hout[l-1][0]; W = Wih + (l-1)*4096;
            b1 = bih + (l-1)*64;  b2 = bhh + (l-1)*64;
            Out = &g_pre[l][0]; K = 64;
        }
        gemm_body(X, W, b1, b2, Out, K, (long)b * TLEN + t0);

        if (kind == 0) {
            __threadfence();
            __syncthreads();
            if (tid == 0) st_rel(&gflag[l][c][b], 1);
        }
        return;
    }

    // ================= SCAN: 2 independent rows, named barriers =================
    const float* Whh_l = (l == 0) ? Whh0 : Whh + (l-1)*4096;
    float* pre  = &g_pre [l][0];
    float* hout = &g_hout[l][0];
    float* hst  = &g_hst [l][0];

    __shared__ __align__(16) float hbuf[2][2][64];   // [row][phase][col]

    const int r    = tid >> 6;            // row within block (0/1)
    const int u    = tid & 63;
    const int W32  = u >> 5;              // warp-half: outputs [32W, 32W+32)
    const int lane = tid & 31;
    const int og   = lane & 7;            // output group (4 outputs)
    const int ks   = lane >> 3;           // k-quarter (16 k)
    const int K0   = 16 * ks;
    const int jo   = 32*W32 + 4*og + ks;  // the output this lane finalizes
    const long b   = 2L*grp + r;
    const int bar  = 1 + r;

    // dep wait (per row)
    if (u == 0) {
        while (ld_acq(&gflag[l][c][b]) == 0) __nanosleep(64);
        if (c > 0) while (ld_acq(&sflag[l][c-1][b]) == 0) __nanosleep(64);
        __threadfence();
    }
    bar_sync(bar);

    // init h
    float h0v = (c == 0) ? 0.f : __ldcg(&hst[b*64 + u]);
    hbuf[r][0][u] = h0v;
    hbuf[r][1][u] = h0v;

    // weights: w2[o][q] = {Whh[32W+4og+o][K0+2q], [K0+2q+1]}  (32 u64)
    u64 w2[4][8];
    #pragma unroll
    for (int o = 0; o < 4; o++) {
        const float4* wr = reinterpret_cast<const float4*>(Whh_l + (32*W32 + 4*og + o)*64 + K0);
        #pragma unroll
        for (int q = 0; q < 4; q++) {
            float4 w = __ldg(&wr[q]);
            w2[o][2*q]   = pk2(w.x, w.y);
            w2[o][2*q+1] = pk2(w.z, w.w);
        }
    }

    const float* prow = pre  + (b * TLEN + t0) * 64 + jo;
    float*       orow = hout + (b * TLEN + t0) * 64 + jo;

    float pb[8];
    #pragma unroll
    for (int q = 0; q < 8; q++) pb[q] = __ldg(&prow[q * 64]);
    bar_sync(bar);

    #pragma unroll 8
    for (int t = 0; t < CT; t++) {
        float cur = pb[t & 7];
        if (t + 8 < CT) pb[t & 7] = __ldg(&prow[(long)(t + 8) * 64]);

        // this lane's k-quarter of h: 16 floats = 4x LDS.128
        const ulonglong2* H2 = reinterpret_cast<const ulonglong2*>(&hbuf[r][t & 1][K0]);
        ulonglong2 hA = H2[0];
        ulonglong2 hB = H2[1];
        ulonglong2 hC = H2[2];
        ulonglong2 hD = H2[3];

        float P[4];
        #pragma unroll
        for (int o = 0; o < 4; o++) {
            u64 a0 = 0ull, a1 = 0ull;
            FMA2(a0, hA.x, w2[o][0], a0);
            FMA2(a1, hA.y, w2[o][1], a1);
            FMA2(a0, hB.x, w2[o][2], a0);
            FMA2(a1, hB.y, w2[o][3], a1);
            FMA2(a0, hC.x, w2[o][4], a0);
            FMA2(a1, hC.y, w2[o][5], a1);
            FMA2(a0, hD.x, w2[o][6], a0);
            FMA2(a1, hD.y, w2[o][7], a1);
            ADD2(a0, a0, a1);
            float lo, hi; upk2(a0, lo, hi);
            P[o] = lo + hi;
        }
        // full k-reduction in-warp (ks lives on lane bits 3,4)
        #pragma unroll
        for (int o = 0; o < 4; o++) {
            P[o] += __shfl_xor_sync(0xffffffffu, P[o], 8);
            P[o] += __shfl_xor_sync(0xffffffffu, P[o], 16);
        }
        // lane finalizes output o = ks (static selection, no dynamic indexing)
        float sum = (ks == 0) ? P[0] : (ks == 1) ? P[1] : (ks == 2) ? P[2] : P[3];
        float h = tanh_fast(cur + sum);

        orow[(long)t * 64] = h;            // 32 distinct cols in one 128B seg
        hbuf[r][(t & 1) ^ 1][jo] = h;      // conflict-free STS.32
        bar_sync(bar);                     // ONE barrier per step
    }

    hst[b*64 + jo] = hbuf[r][0][jo];       // CT even -> final h in phase 0

    __threadfence();
    bar_sync(bar);
    if (u == 0) st_rel(&sflag[l][c][b], 1);
}

extern "C" void kernel_launch(void* const* d_in, const int* in_sizes, int n_in,
                              void* d_out, int out_size)
{
    const float* x    = (const float*)d_in[0];
    const float* Wih0 = (const float*)d_in[1];
    const float* Whh0 = (const float*)d_in[2];
    const float* bih0 = (const float*)d_in[3];
    const float* bhh0 = (const float*)d_in[4];
    const float* Wih  = (const float*)d_in[5];
    const float* Whh  = (const float*)d_in[6];
    const float* bih  = (const float*)d_in[7];
    const float* bhh  = (const float*)d_in[8];
    const float* Wfc  = (const float*)d_in[9];
    const float* bfc  = (const float*)d_in[10];
    float* out = (float*)d_out;

    zero_flags<<<(4*CHUNKS*BATCH + 255)/256, 256>>>();
    mega<<<BLOCKS_TOTAL, 128>>>(x, Wih0, Whh0, bih0, bhh0,
                                Wih, Whh, bih, bhh, Wfc, bfc, out);
}